// round 12
// baseline (speedup 1.0000x reference)
#include <cuda_runtime.h>

// Problem constants (fixed by the reference module)
#define N_  16
#define D_  3
#define H_  160
#define W_  160
#define M_  8
#define K_  10
#define P_  15
#define PM_ 7               // (P-1)/2
#define OH_ (H_ - P_ + 1)   // 146
#define OW_ (W_ - P_ + 1)   // 146
#define MK_ (M_ * K_)       // 80
#define PLANE_ (OH_ * OW_)  // 21316

// Block = (n, k, rg). All 8 m for a given k sample the same (n, channels[k])
// plane: stage 24 input rows in smem once, warp m computes its 10-row band.
// RG=15 row groups (last clamped to y0=136). 5 column bands of 32 (last
// clamped to x0=114); overlapped regions write identical values.
// Each band's 10 rows split into TWO independent 5-row rolling chains
// (rows 0-4 and 5-9) interleaved for 2x memory-level parallelism.
#define HTILE_ 10
#define HHALF_ 5
#define RG_    15
#define SROWS_ 24                      // 10 + 13 tap rows, rounded up
#define SMEM_FLOATS_ (SROWS_ * W_)     // 3840 floats = 15360 B
#define NBLOCKS_ (N_ * K_ * RG_)       // 2400

__global__ __launch_bounds__(256, 7)   // <=37 regs, 7 blocks/SM
void fern_bits_kernel(
    const float* __restrict__ T,
    const float* __restrict__ dx1, const float* __restrict__ dx2,
    const float* __restrict__ dy1, const float* __restrict__ dy2,
    const float* __restrict__ th,  const float* __restrict__ amb,
    const int*   __restrict__ channels,
    float* __restrict__ out)
{
    __shared__ float splane[SMEM_FLOATS_];

    // ---- block decode: bid = (n*K + k)*RG + rg ----
    const int bid = blockIdx.x;
    const int rg  = bid % RG_;
    const int nk  = bid / RG_;
    const int k   = nk % K_;
    const int n   = nk / K_;
    const int ch  = channels[k];

    const int y0 = min(rg * HTILE_, OH_ - HTILE_);   // 0,10,...,136
    // staged plane rows [y0, y0+23]; max = 136+23 = 159 < 160. OK.

    // ---- cooperative staging: linear float4 copy (960 float4s) ----
    const float* __restrict__ img = T + ((size_t)(n * D_ + ch)) * (H_ * W_);
    {
        const float4* __restrict__ g4 = (const float4*)(img + y0 * W_);
        float4* s4 = (float4*)splane;
        for (int i = threadIdx.x; i < SMEM_FLOATS_ / 4; i += 256)
            s4[i] = g4[i];
    }
    __syncthreads();

    // ---- per-warp: one m value ----
    const int m    = threadIdx.x >> 5;
    const int lane = threadIdx.x & 31;
    const int mk   = m * K_ + k;
    const int nmk  = n * MK_ + mk;

    // per-(m,k) parameters (uniform per warp, broadcast loads)
    const float a1x = dx1[mk], a2x = dx2[mk];
    const float a1y = dy1[mk], a2y = dy2[mk];
    const float fl1x = floorf(a1x), fl2x = floorf(a2x);
    const float fl1y = floorf(a1y), fl2y = floorf(a2y);
    const float f1x = a1x - fl1x, f2x = a2x - fl2x;
    const float f1y = a1y - fl1y, f2y = a2y - fl2y;
    const float g1x = 1.0f - f1x, g2x = 1.0f - f2x;
    const float g1y  = 1.0f - f1y;
    const float ng2y = -(1.0f - f2y), nf2y = -f2y;
    const int sx1 = PM_ + (int)fl1x, sx2 = PM_ + (int)fl2x;
    const int sy1 = PM_ + (int)fl1y, sy2 = PM_ + (int)fl2y;

    const float thv = th[mk];
    const float pos = amb[(m * 2 + 0) * K_ + k];
    const float neg = amb[(m * 2 + 1) * K_ + k];
    const float inv = 1.0f / (pos - neg + 1e-29f);
    const float c   = -(thv + neg) * inv;   // v = sat(temp*inv + c)

    // ---- sweep 5 column bands; two independent 5-row chains per band ----
    #pragma unroll 1
    for (int cb = 0; cb < 5; cb++) {
        const int x0 = min(cb * 32, OW_ - 32);   // 0,32,64,96,114
        const int x  = x0 + lane;

        // smem tap bases: sy in [0,12], rows used <= 22 < 24;
        // sx in [0,12], x <= 145 -> col <= 158 < 160.
        const float* s1 = splane + sy1 * W_ + sx1 + x;
        const float* s2 = splane + sy2 * W_ + sx2 + x;
        float* op = out + (size_t)nmk * PLANE_ + y0 * OW_ + x;

        // prologues: chain A starts at input row 0, chain B at input row 5
        float pA1 = g1x * s1[0] + f1x * s1[1];
        float pA2 = g2x * s2[0] + f2x * s2[1];
        float pB1 = g1x * s1[HHALF_ * W_] + f1x * s1[HHALF_ * W_ + 1];
        float pB2 = g2x * s2[HHALF_ * W_] + f2x * s2[HHALF_ * W_ + 1];

        #pragma unroll
        for (int j = 1; j <= HHALF_; j++) {
            const int rA = j;              // input rows 1..5
            const int rB = j + HHALF_;     // input rows 6..10

            // independent tap loads for both chains (2x MLP)
            const float aA0 = s1[rA * W_], aA1 = s1[rA * W_ + 1];
            const float bA0 = s2[rA * W_], bA1 = s2[rA * W_ + 1];
            const float aB0 = s1[rB * W_], aB1 = s1[rB * W_ + 1];
            const float bB0 = s2[rB * W_], bB1 = s2[rB * W_ + 1];

            const float cA1 = g1x * aA0 + f1x * aA1;
            const float cA2 = g2x * bA0 + f2x * bA1;
            const float cB1 = g1x * aB0 + f1x * aB1;
            const float cB2 = g2x * bB0 + f2x * bB1;

            float tA = g1y * pA1;
            tA = fmaf(f1y,  cA1, tA);
            tA = fmaf(ng2y, pA2, tA);
            tA = fmaf(nf2y, cA2, tA);
            pA1 = cA1; pA2 = cA2;

            float tB = g1y * pB1;
            tB = fmaf(f1y,  cB1, tB);
            tB = fmaf(ng2y, pB2, tB);
            tB = fmaf(nf2y, cB2, tB);
            pB1 = cB1; pB2 = cB2;

            if (fabsf(tA) < 1e-5f) tA = 0.0f;
            if (fabsf(tB) < 1e-5f) tB = 0.0f;
            op[(j - 1) * OW_]          = __saturatef(fmaf(tA, inv, c));
            op[(j - 1 + HHALF_) * OW_] = __saturatef(fmaf(tB, inv, c));
        }
    }
}

extern "C" void kernel_launch(void* const* d_in, const int* in_sizes, int n_in,
                              void* d_out, int out_size)
{
    const float* T        = (const float*)d_in[0];
    const float* dx1      = (const float*)d_in[1];
    const float* dx2      = (const float*)d_in[2];
    const float* dy1      = (const float*)d_in[3];
    const float* dy2      = (const float*)d_in[4];
    const float* th       = (const float*)d_in[5];
    const float* amb      = (const float*)d_in[6];
    const int*   channels = (const int*)  d_in[7];
    float* out = (float*)d_out;

    fern_bits_kernel<<<NBLOCKS_, 256>>>(
        T, dx1, dx2, dy1, dy2, th, amb, channels, out);
}

// round 13
// speedup vs baseline: 1.0458x; 1.0458x over previous
#include <cuda_runtime.h>

// Problem constants (fixed by the reference module)
#define N_  16
#define D_  3
#define H_  160
#define W_  160
#define M_  8
#define K_  10
#define P_  15
#define PM_ 7               // (P-1)/2
#define OH_ (H_ - P_ + 1)   // 146
#define OW_ (W_ - P_ + 1)   // 146
#define MK_ (M_ * K_)       // 80
#define PLANE_ (OH_ * OW_)  // 21316

// Block = (n, k, rg). All 8 m for a given k sample the same (n, channels[k])
// plane: stage 24 input rows in smem once, warp m computes its 10-row band.
// RG=15 row groups (last clamped to y0=136). 5 column bands of 32 (last
// clamped to x0=114); overlapped regions write identical values.
// Each band's 10 rows split into TWO independent 5-row rolling chains
// (rows 0-4 and 5-9) interleaved for 2x memory-level parallelism.
// launch_bounds(256,6) -> 40-reg budget so both chains actually get regs.
#define HTILE_ 10
#define HHALF_ 5
#define RG_    15
#define SROWS_ 24                      // 10 + 13 tap rows, rounded up
#define SMEM_FLOATS_ (SROWS_ * W_)     // 3840 floats = 15360 B
#define NBLOCKS_ (N_ * K_ * RG_)       // 2400

__global__ __launch_bounds__(256, 6)   // 40 regs granted, 6 blocks/SM
void fern_bits_kernel(
    const float* __restrict__ T,
    const float* __restrict__ dx1, const float* __restrict__ dx2,
    const float* __restrict__ dy1, const float* __restrict__ dy2,
    const float* __restrict__ th,  const float* __restrict__ amb,
    const int*   __restrict__ channels,
    float* __restrict__ out)
{
    __shared__ float splane[SMEM_FLOATS_];

    // ---- block decode: bid = (n*K + k)*RG + rg ----
    const int bid = blockIdx.x;
    const int rg  = bid % RG_;
    const int nk  = bid / RG_;
    const int k   = nk % K_;
    const int n   = nk / K_;
    const int ch  = channels[k];

    const int y0 = min(rg * HTILE_, OH_ - HTILE_);   // 0,10,...,136
    // staged plane rows [y0, y0+23]; max = 136+23 = 159 < 160. OK.

    // ---- cooperative staging: linear float4 copy (960 float4s) ----
    const float* __restrict__ img = T + ((size_t)(n * D_ + ch)) * (H_ * W_);
    {
        const float4* __restrict__ g4 = (const float4*)(img + y0 * W_);
        float4* s4 = (float4*)splane;
        for (int i = threadIdx.x; i < SMEM_FLOATS_ / 4; i += 256)
            s4[i] = g4[i];
    }
    __syncthreads();

    // ---- per-warp: one m value ----
    const int m    = threadIdx.x >> 5;
    const int lane = threadIdx.x & 31;
    const int mk   = m * K_ + k;
    const int nmk  = n * MK_ + mk;

    // per-(m,k) parameters (uniform per warp, broadcast loads)
    const float a1x = dx1[mk], a2x = dx2[mk];
    const float a1y = dy1[mk], a2y = dy2[mk];
    const float fl1x = floorf(a1x), fl2x = floorf(a2x);
    const float fl1y = floorf(a1y), fl2y = floorf(a2y);
    const float f1x = a1x - fl1x, f2x = a2x - fl2x;
    const float f1y = a1y - fl1y, f2y = a2y - fl2y;
    const float g1x = 1.0f - f1x, g2x = 1.0f - f2x;
    const float g1y  = 1.0f - f1y;
    const float ng2y = -(1.0f - f2y), nf2y = -f2y;
    const int sx1 = PM_ + (int)fl1x, sx2 = PM_ + (int)fl2x;
    const int sy1 = PM_ + (int)fl1y, sy2 = PM_ + (int)fl2y;

    const float thv = th[mk];
    const float pos = amb[(m * 2 + 0) * K_ + k];
    const float neg = amb[(m * 2 + 1) * K_ + k];
    const float inv = 1.0f / (pos - neg + 1e-29f);
    const float c   = -(thv + neg) * inv;   // v = sat(temp*inv + c)

    // ---- sweep 5 column bands; two independent 5-row chains per band ----
    #pragma unroll 1
    for (int cb = 0; cb < 5; cb++) {
        const int x0 = min(cb * 32, OW_ - 32);   // 0,32,64,96,114
        const int x  = x0 + lane;

        // smem tap bases: sy in [0,12], rows used <= 22 < 24;
        // sx in [0,12], x <= 145 -> col <= 158 < 160.
        const float* s1 = splane + sy1 * W_ + sx1 + x;
        const float* s2 = splane + sy2 * W_ + sx2 + x;
        float* op = out + (size_t)nmk * PLANE_ + y0 * OW_ + x;

        // prologues: chain A starts at input row 0, chain B at input row 5
        float pA1 = g1x * s1[0] + f1x * s1[1];
        float pA2 = g2x * s2[0] + f2x * s2[1];
        float pB1 = g1x * s1[HHALF_ * W_] + f1x * s1[HHALF_ * W_ + 1];
        float pB2 = g2x * s2[HHALF_ * W_] + f2x * s2[HHALF_ * W_ + 1];

        #pragma unroll
        for (int j = 1; j <= HHALF_; j++) {
            const int rA = j;              // input rows 1..5
            const int rB = j + HHALF_;     // input rows 6..10

            // independent tap loads for both chains (2x MLP)
            const float aA0 = s1[rA * W_], aA1 = s1[rA * W_ + 1];
            const float bA0 = s2[rA * W_], bA1 = s2[rA * W_ + 1];
            const float aB0 = s1[rB * W_], aB1 = s1[rB * W_ + 1];
            const float bB0 = s2[rB * W_], bB1 = s2[rB * W_ + 1];

            const float cA1 = g1x * aA0 + f1x * aA1;
            const float cA2 = g2x * bA0 + f2x * bA1;
            const float cB1 = g1x * aB0 + f1x * aB1;
            const float cB2 = g2x * bB0 + f2x * bB1;

            float tA = g1y * pA1;
            tA = fmaf(f1y,  cA1, tA);
            tA = fmaf(ng2y, pA2, tA);
            tA = fmaf(nf2y, cA2, tA);
            pA1 = cA1; pA2 = cA2;

            float tB = g1y * pB1;
            tB = fmaf(f1y,  cB1, tB);
            tB = fmaf(ng2y, pB2, tB);
            tB = fmaf(nf2y, cB2, tB);
            pB1 = cB1; pB2 = cB2;

            if (fabsf(tA) < 1e-5f) tA = 0.0f;
            if (fabsf(tB) < 1e-5f) tB = 0.0f;
            op[(j - 1) * OW_]          = __saturatef(fmaf(tA, inv, c));
            op[(j - 1 + HHALF_) * OW_] = __saturatef(fmaf(tB, inv, c));
        }
    }
}

extern "C" void kernel_launch(void* const* d_in, const int* in_sizes, int n_in,
                              void* d_out, int out_size)
{
    const float* T        = (const float*)d_in[0];
    const float* dx1      = (const float*)d_in[1];
    const float* dx2      = (const float*)d_in[2];
    const float* dy1      = (const float*)d_in[3];
    const float* dy2      = (const float*)d_in[4];
    const float* th       = (const float*)d_in[5];
    const float* amb      = (const float*)d_in[6];
    const int*   channels = (const int*)  d_in[7];
    float* out = (float*)d_out;

    fern_bits_kernel<<<NBLOCKS_, 256>>>(
        T, dx1, dx2, dy1, dy2, th, amb, channels, out);
}